// round 7
// baseline (speedup 1.0000x reference)
#include <cuda_runtime.h>

// Problem constants: B=256, T=2048, I=2, H=128, 3H=384
#define BB 256
#define TT 2048
#define HH 128
#define NTHREADS 384

__device__ int d_order[BB];

// Plain descending-length order (R2-proven best): wave 1 = 148 longest,
// wave-2 CTAs work-stolen in bid order = LPT.
__global__ void order_kernel(const int* __restrict__ lengths) {
    int i = threadIdx.x;
    int li = lengths[i];
    int rank = 0;
    #pragma unroll 8
    for (int j = 0; j < BB; j++) {
        int lj = lengths[j];
        rank += (lj > li) || (lj == li && j < i);
    }
    d_order[rank] = i;
}

// ---- packed f32x2 helpers ----
__device__ __forceinline__ unsigned long long fma2(unsigned long long a,
                                                   unsigned long long b,
                                                   unsigned long long c) {
    unsigned long long d;
    asm("fma.rn.f32x2 %0, %1, %2, %3;" : "=l"(d) : "l"(a), "l"(b), "l"(c));
    return d;
}
__device__ __forceinline__ unsigned long long add2(unsigned long long a,
                                                   unsigned long long b) {
    unsigned long long d;
    asm("add.rn.f32x2 %0, %1, %2;" : "=l"(d) : "l"(a), "l"(b));
    return d;
}
__device__ __forceinline__ unsigned long long pack2(float x, float y) {
    unsigned long long r;
    asm("mov.b64 %0, {%1, %2};" : "=l"(r) : "f"(x), "f"(y));
    return r;
}
__device__ __forceinline__ void unpack2(unsigned long long v, float& x, float& y) {
    asm("mov.b64 {%0, %1}, %2;" : "=f"(x), "=f"(y) : "l"(v));
}

__device__ __forceinline__ float tanh_fast(float v) {
    float r;
    asm("tanh.approx.f32 %0, %1;" : "=f"(r) : "f"(v));
    return r;
}

// Roles: tid 0..127 -> z-rows (128+j); 128..255 -> n-rows (256+j);
// 256..383 -> r-rows (j) + combiner (highest warps = arbiter priority).
// Trio t = {warp t, warp t+4, warp t+8} syncs via named barrier 1+t (96 thr).
//
// Gate math is distributed: the z-warp computes its gate's tanh itself
// (z_t), the n-warp pre-reduces (c = xn + gn/2, d = gn/2), and the combiner
// computes r_t BEFORE the barrier (depends only on its own matvec).
// Post-barrier serial chain: LDS -> 1 MUFU -> 3 fma -> STS.
__global__ void __launch_bounds__(NTHREADS, 1)
gru_kernel(const float* __restrict__ x,        // [B, T, 2]
           const int*   __restrict__ lengths,  // [B]
           const float* __restrict__ W_ih,     // [384, 2]
           const float* __restrict__ W_hh,     // [384, 128]
           const float* __restrict__ b_ih,     // [384]
           const float* __restrict__ b_hh,     // [384]
           const float* __restrict__ head_w,   // [128]
           const float* __restrict__ head_b,   // [1]
           float*       __restrict__ out)      // [B, 1]
{
    __shared__ __align__(16) float sh_x[TT * 2];     // 16 KB
    __shared__ __align__(16) float sh_h[2][HH];      // ping-pong hidden state
    __shared__ float  sh_zt[HH];                     // z_t from z-warps
    __shared__ __align__(8) float2 sh_cd[HH];        // (c, d) from n-warps
    __shared__ float sh_red[4];

    const int tid = threadIdx.x;
    const int b = d_order[blockIdx.x];
    const int len = lengths[b];

    const int role = tid >> 7;            // 0=z, 1=n, 2=r/combiner
    const int j = tid & 127;
    const int row = (role == 0) ? (HH + j) : (role == 1) ? (2 * HH + j) : j;
    const int bar_id = 1 + ((tid >> 5) & 3);

    // --- load input prefix into shared ---
    {
        const float4* xs = reinterpret_cast<const float4*>(x + (size_t)b * (TT * 2));
        float4* xd = reinterpret_cast<float4*>(sh_x);
        int nq = (len * 2 + 3) >> 2;
        for (int q = tid; q < nq; q += NTHREADS) xd[q] = xs[q];
    }

    // --- W_hh row into 64 packed f32x2 registers ---
    unsigned long long w[64];
    {
        const unsigned long long* wrow =
            reinterpret_cast<const unsigned long long*>(W_hh + (size_t)row * HH);
        #pragma unroll
        for (int t = 0; t < 64; t++) w[t] = wrow[t];
    }
    const float bhh = b_hh[row];

    // Each thread projects ONLY its own row's input. sigma prescale (0.5x)
    // folded into r and z rows; n row unscaled.
    const float scale = (role == 1) ? 1.0f : 0.5f;
    float pw0, pw1, pb;
    {
        float2 t2 = *reinterpret_cast<const float2*>(W_ih + (size_t)row * 2);
        pw0 = scale * t2.x;
        pw1 = scale * t2.y;
        pb  = scale * b_ih[row];
    }
    float hw = 0.f, h = 0.0f;
    if (role == 2) {
        hw = head_w[j];
        sh_h[0][j] = 0.0f;
    }
    __syncthreads();

    int cur = 0;
    for (int t = 0; t < len; t++) {
        // Own-row input projection (h-independent, uniform on all warps).
        float2 xt = *reinterpret_cast<const float2*>(sh_x + 2 * t);
        float xp = fmaf(pw0, xt.x, fmaf(pw1, xt.y, pb));

        // gh = b_hh[row] + W_hh[row] . h   (4 FMA2 chains)
        unsigned long long acc0 = pack2(bhh, 0.0f);
        unsigned long long acc1 = pack2(0.0f, 0.0f);
        unsigned long long acc2 = acc1, acc3 = acc1;
        const ulonglong2* h2 = reinterpret_cast<const ulonglong2*>(sh_h[cur]);
        #pragma unroll
        for (int k = 0; k < 16; k++) {
            ulonglong2 ha = h2[2 * k];
            ulonglong2 hb = h2[2 * k + 1];
            acc0 = fma2(w[4 * k + 0], ha.x, acc0);
            acc1 = fma2(w[4 * k + 1], ha.y, acc1);
            acc2 = fma2(w[4 * k + 2], hb.x, acc2);
            acc3 = fma2(w[4 * k + 3], hb.y, acc3);
        }
        unsigned long long s = add2(add2(acc0, acc1), add2(acc2, acc3));
        float slo, shi;
        unpack2(s, slo, shi);
        float gh = slo + shi;

        // Unified gate prologue on ALL warps (straight-line, no branch):
        //   role 0: tv = z_t = tanh(0.5*gz + xz2)
        //   role 2: tv = r_t = tanh(0.5*gr + xr2)
        //   role 1: c = xn + 0.5*gn, d = 0.5*gn (tv unused)
        float tv = tanh_fast(fmaf(0.5f, gh, xp));
        float d = 0.5f * gh;
        float c = xp + d;

        if (role != 2) {
            if (role == 0) sh_zt[j] = tv;               // warp-uniform select
            else           sh_cd[j] = make_float2(c, d);
            asm volatile("bar.arrive %0, 96;" :: "r"(bar_id) : "memory");
        } else {
            asm volatile("bar.sync %0, 96;" :: "r"(bar_id) : "memory");
            float z_t = sh_zt[j];
            float2 cd = sh_cd[j];
            float n = tanh_fast(fmaf(tv, cd.y, cd.x));  // tanh(xn + r*gn)
            h = 0.5f * fmaf(z_t, h - n, h + n);         // (1-z)*n + z*h
            sh_h[cur ^ 1][j] = h;
        }
        __syncthreads();
        cur ^= 1;
    }

    // --- head: out[b] = sum_j h[j]*head_w[j] + head_b ---
    if (role == 2) {
        float v = h * hw;
        #pragma unroll
        for (int o = 16; o > 0; o >>= 1) v += __shfl_down_sync(0xffffffffu, v, o);
        if ((tid & 31) == 0) sh_red[(tid >> 5) - 8] = v;
    }
    __syncthreads();
    if (tid == 256) {
        out[b] = (sh_red[0] + sh_red[1]) + (sh_red[2] + sh_red[3]) + head_b[0];
    }
}

extern "C" void kernel_launch(void* const* d_in, const int* in_sizes, int n_in,
                              void* d_out, int out_size) {
    const float* x      = (const float*)d_in[0];
    const int*   len    = (const int*)  d_in[1];
    const float* W_ih   = (const float*)d_in[2];
    const float* W_hh   = (const float*)d_in[3];
    const float* b_ih   = (const float*)d_in[4];
    const float* b_hh   = (const float*)d_in[5];
    const float* head_w = (const float*)d_in[6];
    const float* head_b = (const float*)d_in[7];
    float* out = (float*)d_out;

    order_kernel<<<1, BB>>>(len);
    gru_kernel<<<BB, NTHREADS>>>(x, len, W_ih, W_hh, b_ih, b_hh,
                                 head_w, head_b, out);
}

// round 8
// speedup vs baseline: 1.0371x; 1.0371x over previous
#include <cuda_runtime.h>

// Problem constants: B=256, T=2048, I=2, H=128, 3H=384
#define BB 256
#define TT 2048
#define HH 128
#define NTHREADS 384

__device__ int d_order[BB];

// Plain descending-length order (R2-proven best): wave 1 = 148 longest,
// wave-2 CTAs work-stolen in bid order = LPT.
__global__ void order_kernel(const int* __restrict__ lengths) {
    int i = threadIdx.x;
    int li = lengths[i];
    int rank = 0;
    #pragma unroll 8
    for (int j = 0; j < BB; j++) {
        int lj = lengths[j];
        rank += (lj > li) || (lj == li && j < i);
    }
    d_order[rank] = i;
}

// ---- packed f32x2 helpers ----
__device__ __forceinline__ unsigned long long fma2(unsigned long long a,
                                                   unsigned long long b,
                                                   unsigned long long c) {
    unsigned long long d;
    asm("fma.rn.f32x2 %0, %1, %2, %3;" : "=l"(d) : "l"(a), "l"(b), "l"(c));
    return d;
}
__device__ __forceinline__ unsigned long long add2(unsigned long long a,
                                                   unsigned long long b) {
    unsigned long long d;
    asm("add.rn.f32x2 %0, %1, %2;" : "=l"(d) : "l"(a), "l"(b));
    return d;
}
__device__ __forceinline__ unsigned long long pack2(float x, float y) {
    unsigned long long r;
    asm("mov.b64 %0, {%1, %2};" : "=l"(r) : "f"(x), "f"(y));
    return r;
}
__device__ __forceinline__ void unpack2(unsigned long long v, float& x, float& y) {
    asm("mov.b64 {%0, %1}, %2;" : "=f"(x), "=f"(y) : "l"(v));
}

__device__ __forceinline__ float tanh_fast(float v) {
    float r;
    asm("tanh.approx.f32 %0, %1;" : "=f"(r) : "f"(v));
    return r;
}

// Roles: tid 0..127 -> z-rows (128+j); 128..255 -> n-rows (256+j);
// 256..383 -> r-rows (j) + combiner (highest warps = arbiter priority).
// Trio t = {warp t, warp t+4, warp t+8} lives on ONE SMSP; syncs via named
// barrier 1+t (96 thr).
//
// Overlap plan: combiner's r-tanh runs BEFORE its bar.sync (inside the
// wait-for-producers window); producers prefetch x-proj(t+1) between
// bar.arrive and __syncthreads. Producer-z folds its x-proj into the STS'd
// value; producer-n pre-reduces (c, d). Combiner post-bar chain:
// LDS.128 {c,d,z'} -> 2 parallel MUFU -> 3 fma -> STS h.
__global__ void __launch_bounds__(NTHREADS, 1)
gru_kernel(const float* __restrict__ x,        // [B, T, 2]
           const int*   __restrict__ lengths,  // [B]
           const float* __restrict__ W_ih,     // [384, 2]
           const float* __restrict__ W_hh,     // [384, 128]
           const float* __restrict__ b_ih,     // [384]
           const float* __restrict__ b_hh,     // [384]
           const float* __restrict__ head_w,   // [128]
           const float* __restrict__ head_b,   // [1]
           float*       __restrict__ out)      // [B, 1]
{
    __shared__ __align__(16) float sh_x[TT * 2 + 4];  // +pad for t+1 prefetch
    __shared__ __align__(16) float sh_h[2][HH];       // ping-pong hidden state
    __shared__ __align__(16) float4 sh_g[HH];         // {c, d, z', pad} per j
    __shared__ float sh_red[4];

    const int tid = threadIdx.x;
    const int b = d_order[blockIdx.x];
    const int len = lengths[b];

    const int role = tid >> 7;            // 0=z, 1=n, 2=r/combiner
    const int j = tid & 127;
    const int row = (role == 0) ? (HH + j) : (role == 1) ? (2 * HH + j) : j;
    const int bar_id = 1 + ((tid >> 5) & 3);

    // --- load input prefix into shared ---
    {
        const float4* xs = reinterpret_cast<const float4*>(x + (size_t)b * (TT * 2));
        float4* xd = reinterpret_cast<float4*>(sh_x);
        int nq = (len * 2 + 3) >> 2;
        for (int q = tid; q < nq; q += NTHREADS) xd[q] = xs[q];
        if (tid < 4) sh_x[TT * 2 + tid] = 0.0f;        // prefetch pad
    }

    // --- W_hh row into 64 packed f32x2 registers ---
    unsigned long long w[64];
    {
        const unsigned long long* wrow =
            reinterpret_cast<const unsigned long long*>(W_hh + (size_t)row * HH);
        #pragma unroll
        for (int t = 0; t < 64; t++) w[t] = wrow[t];
    }
    const unsigned long long bhh2 = pack2(b_hh[row], 0.0f);
    const unsigned long long zero2 = pack2(0.0f, 0.0f);

    // Own-row input projection constants. sigma prescale (0.5) folded into
    // r and z rows; n row unscaled.
    const float scale = (role == 1) ? 1.0f : 0.5f;
    float pw0, pw1, pb;
    {
        float2 t2 = *reinterpret_cast<const float2*>(W_ih + (size_t)row * 2);
        pw0 = scale * t2.x;
        pw1 = scale * t2.y;
        pb  = scale * b_ih[row];
    }
    float hw = 0.f, h = 0.0f;
    if (role == 2) {
        hw = head_w[j];
        sh_h[0][j] = 0.0f;
    }
    __syncthreads();

    // x-proj for t = 0 (all threads).
    float2 xt0 = *reinterpret_cast<const float2*>(sh_x);
    float xp = fmaf(pw0, xt0.x, fmaf(pw1, xt0.y, pb));

    int cur = 0;
    for (int t = 0; t < len; t++) {
        // gh = b_hh[row] + W_hh[row] . h   (4 FMA2 chains)
        unsigned long long acc0 = bhh2;
        unsigned long long acc1 = zero2, acc2 = zero2, acc3 = zero2;
        const ulonglong2* h2 = reinterpret_cast<const ulonglong2*>(sh_h[cur]);
        #pragma unroll
        for (int k = 0; k < 16; k++) {
            ulonglong2 ha = h2[2 * k];
            ulonglong2 hb = h2[2 * k + 1];
            acc0 = fma2(w[4 * k + 0], ha.x, acc0);
            acc1 = fma2(w[4 * k + 1], ha.y, acc1);
            acc2 = fma2(w[4 * k + 2], hb.x, acc2);
            acc3 = fma2(w[4 * k + 3], hb.y, acc3);
        }
        unsigned long long s = add2(add2(acc0, acc1), add2(acc2, acc3));
        float slo, shi;
        unpack2(s, slo, shi);
        float gh = slo + shi;

        if (role != 2) {
            // Producer tails (cheap: <=2 fma + STS), then prefetch next xp
            // inside the bar2 wait window.
            if (role == 0) {
                sh_g[j].z = fmaf(0.5f, gh, xp);        // z' = 0.5*gz + xz2
            } else {
                float dnn = 0.5f * gh;                 // d = 0.5*gn
                float2 cd = make_float2(xp + dnn, dnn);
                *reinterpret_cast<float2*>(&sh_g[j]) = cd;   // {c, d}
            }
            asm volatile("bar.arrive %0, 96;" :: "r"(bar_id) : "memory");
            float2 xt = *reinterpret_cast<const float2*>(sh_x + 2 * (t + 1));
            xp = fmaf(pw0, xt.x, fmaf(pw1, xt.y, pb));
            __syncthreads();
        } else {
            // r_t depends only on own matvec: compute during producer wait.
            float r_t = tanh_fast(fmaf(0.5f, gh, xp));
            asm volatile("bar.sync %0, 96;" :: "r"(bar_id) : "memory");
            float4 g = sh_g[j];                        // {c, d, z', pad}
            float z_t = tanh_fast(g.z);
            float n = tanh_fast(fmaf(r_t, g.y, g.x));  // tanh(xn + r*gn)
            h = 0.5f * fmaf(z_t, h - n, h + n);        // (1-z)*n + z*h
            sh_h[cur ^ 1][j] = h;
            __syncthreads();
            float2 xt = *reinterpret_cast<const float2*>(sh_x + 2 * (t + 1));
            xp = fmaf(pw0, xt.x, fmaf(pw1, xt.y, pb));
        }
        cur ^= 1;
    }

    // --- head: out[b] = sum_j h[j]*head_w[j] + head_b ---
    if (role == 2) {
        float v = h * hw;
        #pragma unroll
        for (int o = 16; o > 0; o >>= 1) v += __shfl_down_sync(0xffffffffu, v, o);
        if ((tid & 31) == 0) sh_red[(tid >> 5) - 8] = v;
    }
    __syncthreads();
    if (tid == 256) {
        out[b] = (sh_red[0] + sh_red[1]) + (sh_red[2] + sh_red[3]) + head_b[0];
    }
}

extern "C" void kernel_launch(void* const* d_in, const int* in_sizes, int n_in,
                              void* d_out, int out_size) {
    const float* x      = (const float*)d_in[0];
    const int*   len    = (const int*)  d_in[1];
    const float* W_ih   = (const float*)d_in[2];
    const float* W_hh   = (const float*)d_in[3];
    const float* b_ih   = (const float*)d_in[4];
    const float* b_hh   = (const float*)d_in[5];
    const float* head_w = (const float*)d_in[6];
    const float* head_b = (const float*)d_in[7];
    float* out = (float*)d_out;

    order_kernel<<<1, BB>>>(len);
    gru_kernel<<<BB, NTHREADS>>>(x, len, W_ih, W_hh, b_ih, b_hh,
                                 head_w, head_b, out);
}